// round 7
// baseline (speedup 1.0000x reference)
#include <cuda_runtime.h>
#include <cuda_bf16.h>

// LorenzSDE ShARK integrator, B = 4,194,304, 5 steps, additive noise.
//   z1 = y + g*H
//   z2 = y + (5/6)*dt*f(z1) + g*((5/6)*W + H)
//   y' = y + dt*(0.4*f(z1) + 0.6*f(z2)) + g*W
// with g*W = 2*sqrt(dt)*dW_std, g*H = 2*sqrt(dt/12)*dH_std.
//
// Memory-bound: 604 MB total traffic. Strategy: smem-staged, fully
// coalesced float4 streaming; all 5 steps fused in registers.

#define BATCH_TOTAL 4194304
#define NSTEP 5
#define BLK 256                    // batch elements per block == threads per block

__device__ __forceinline__ void lorenz_drift(float x, float y, float z,
                                             float& fx, float& fy, float& fz) {
    fx = 10.0f * (y - x);
    fy = x * (28.0f - z) - y;
    fz = x * y - (8.0f / 3.0f) * z;
}

__global__ __launch_bounds__(BLK)
void lorenz_shark_kernel(const float* __restrict__ x,
                         const float* __restrict__ dW,
                         const float* __restrict__ dH,
                         float* __restrict__ out) {
    __shared__ float s_x[BLK * 3];            //  3 KB
    __shared__ float s_w[BLK * NSTEP * 3];    // 15 KB
    __shared__ float s_h[BLK * NSTEP * 3];    // 15 KB

    const int tid = threadIdx.x;
    const long long base = (long long)blockIdx.x * BLK;

    // Block-contiguous slices; base*3 floats = 3072B-aligned, base*15 = 15360B-aligned.
    const float4* __restrict__ x4 = (const float4*)(x  + base * 3);
    const float4* __restrict__ w4 = (const float4*)(dW + base * 15);
    const float4* __restrict__ h4 = (const float4*)(dH + base * 15);
    float4* sx4 = (float4*)s_x;
    float4* sw4 = (float4*)s_w;
    float4* sh4 = (float4*)s_h;

    // Coalesced staging: 192 float4 (x), 960 float4 each (dW, dH).
    // Issue all independent global loads; compiler batches for MLP.
    if (tid < 192) sx4[tid] = x4[tid];
#pragma unroll
    for (int i = 0; i < 3; i++) sw4[tid + i * BLK] = w4[tid + i * BLK];
    if (tid < 192) sw4[tid + 3 * BLK] = w4[tid + 3 * BLK];
#pragma unroll
    for (int i = 0; i < 3; i++) sh4[tid + i * BLK] = h4[tid + i * BLK];
    if (tid < 192) sh4[tid + 3 * BLK] = h4[tid + 3 * BLK];
    __syncthreads();

    // Per-thread state (stride-3 smem reads: 3 coprime 32 -> conflict-free).
    float y0 = s_x[tid * 3 + 0];
    float y1 = s_x[tid * 3 + 1];
    float y2 = s_x[tid * 3 + 2];

    const float dt    = 0.01f;
    const float cW    = 0.2f;            // NOISE * sqrt(dt)
    const float cH    = 0.057735026919f; // NOISE * sqrt(dt/12)
    const float c56dt = (5.0f / 6.0f) * 0.01f;
    const float c56   = 5.0f / 6.0f;

#pragma unroll
    for (int s = 0; s < NSTEP; s++) {
        // stride-15 smem reads: 15 coprime 32 -> conflict-free
        const int wb = tid * (NSTEP * 3) + s * 3;
        float w0 = cW * s_w[wb + 0];
        float w1 = cW * s_w[wb + 1];
        float w2 = cW * s_w[wb + 2];
        float h0 = cH * s_h[wb + 0];
        float h1 = cH * s_h[wb + 1];
        float h2 = cH * s_h[wb + 2];

        // z1 = y + h
        float z0 = y0 + h0, z1 = y1 + h1, z2 = y2 + h2;
        float f10, f11, f12;
        lorenz_drift(z0, z1, z2, f10, f11, f12);

        // z2 = y + (5/6)dt*f1 + (5/6)*w + h
        float u0 = y0 + c56dt * f10 + c56 * w0 + h0;
        float u1 = y1 + c56dt * f11 + c56 * w1 + h1;
        float u2 = y2 + c56dt * f12 + c56 * w2 + h2;
        float f20, f21, f22;
        lorenz_drift(u0, u1, u2, f20, f21, f22);

        // y = y + dt*(0.4*f1 + 0.6*f2) + w
        y0 = y0 + dt * (0.4f * f10 + 0.6f * f20) + w0;
        y1 = y1 + dt * (0.4f * f11 + 0.6f * f21) + w1;
        y2 = y2 + dt * (0.4f * f12 + 0.6f * f22) + w2;
    }

    // Stage result (own slots only -> no hazard), then coalesced store.
    s_x[tid * 3 + 0] = y0;
    s_x[tid * 3 + 1] = y1;
    s_x[tid * 3 + 2] = y2;
    __syncthreads();

    float4* o4 = (float4*)(out + base * 3);
    if (tid < 192) o4[tid] = sx4[tid];
}

extern "C" void kernel_launch(void* const* d_in, const int* in_sizes, int n_in,
                              void* d_out, int out_size) {
    const float* x  = (const float*)d_in[0];   // [B, 3]
    const float* dW = (const float*)d_in[1];   // [B, 5, 3]
    const float* dH = (const float*)d_in[2];   // [B, 5, 3]
    float* out = (float*)d_out;                // [B, 3]

    const int nblocks = BATCH_TOTAL / BLK;     // 16384
    lorenz_shark_kernel<<<nblocks, BLK>>>(x, dW, dH, out);
}